// round 14
// baseline (speedup 1.0000x reference)
#include <cuda_runtime.h>
#include <cuda_bf16.h>
#include <cstdint>

#define NB 8
#define C 512
#define T 4096
#define GROUPS 32
#define CPG (C / GROUPS)      // 16
#define GSZ (CPG * T)         // 65536 elements per group

// Scratch (device globals; no allocations allowed)
__device__ float g_sc[NB * C];                         // GN scale  per (n,c)
__device__ float g_sb[NB * C];                         // GN shift  per (n,c)
__device__ __nv_bfloat16 g_q[(size_t)NB * C * T];      // [N][C][T]
__device__ __nv_bfloat16 g_k[(size_t)NB * C * T];      // [N][C][T]
__device__ __nv_bfloat16 g_v[(size_t)NB * C * T];      // [N][C][T]
__device__ __nv_bfloat16 g_o[(size_t)NB * T * C];      // [N][T][C]
__device__ __nv_bfloat16 g_p[(size_t)NB * T * T];      // [N][T][T] bf16 exp(S)
__device__ float g_lp[(size_t)NB * 32 * T];            // partial row sums
__device__ float g_li[NB * T];                         // 1 / row sum

// ---------------------------------------------------------------------------
// GroupNorm stats: one block per (n, group); writes per-channel scale/shift
// ---------------------------------------------------------------------------
__global__ void __launch_bounds__(256) gn_stats(const float* __restrict__ x,
                                                const float* __restrict__ w,
                                                const float* __restrict__ b) {
    int n = blockIdx.x >> 5;
    int g = blockIdx.x & 31;
    const float4* xp = (const float4*)(x + ((size_t)n * C + g * CPG) * T);
    const int NV = GSZ / 4;

    float s = 0.f, s2 = 0.f;
    for (int i = threadIdx.x; i < NV; i += 256) {
        float4 v = xp[i];
        s  += v.x + v.y + v.z + v.w;
        s2 += v.x * v.x + v.y * v.y + v.z * v.z + v.w * v.w;
    }
    __shared__ float rs[32], rs2[32];
    int lid = threadIdx.x & 31, wid = threadIdx.x >> 5;
#pragma unroll
    for (int o = 16; o; o >>= 1) {
        s  += __shfl_xor_sync(0xffffffffu, s, o);
        s2 += __shfl_xor_sync(0xffffffffu, s2, o);
    }
    if (lid == 0) { rs[wid] = s; rs2[wid] = s2; }
    __syncthreads();
    if (wid == 0) {
        s  = (lid < 8) ? rs[lid]  : 0.f;
        s2 = (lid < 8) ? rs2[lid] : 0.f;
#pragma unroll
        for (int o = 4; o; o >>= 1) {
            s  += __shfl_xor_sync(0xffffffffu, s, o);
            s2 += __shfl_xor_sync(0xffffffffu, s2, o);
        }
        if (lid == 0) { rs[0] = s; rs2[0] = s2; }
    }
    __syncthreads();
    float mean = rs[0] * (1.f / GSZ);
    float var  = rs2[0] * (1.f / GSZ) - mean * mean;
    float inv  = rsqrtf(var + 1e-5f);

    if (threadIdx.x < CPG) {
        int c = g * CPG + threadIdx.x;
        float scv = w[c] * inv;
        g_sc[n * C + c] = scv;
        g_sb[n * C + c] = b[c] - mean * scv;
    }
}

// ===========================================================================
// Common helpers
// ===========================================================================
#define BSKC 20
#define KTS  68
#define BSMW 2560

__device__ __forceinline__ uint32_t packbf(float lo, float hi) {
    __nv_bfloat162 h = __float22bfloat162_rn(make_float2(lo, hi));
    return *(uint32_t*)&h;
}

__device__ __forceinline__ void ldsm_x4(uint32_t a[4], uint32_t addr) {
    asm volatile("ldmatrix.sync.aligned.m8n8.x4.shared.b16 {%0,%1,%2,%3}, [%4];"
                 : "=r"(a[0]), "=r"(a[1]), "=r"(a[2]), "=r"(a[3]) : "r"(addr));
}
__device__ __forceinline__ void ldsm_x4t(uint32_t a[4], uint32_t addr) {
    asm volatile("ldmatrix.sync.aligned.m8n8.x4.trans.shared.b16 {%0,%1,%2,%3}, [%4];"
                 : "=r"(a[0]), "=r"(a[1]), "=r"(a[2]), "=r"(a[3]) : "r"(addr));
}
__device__ __forceinline__ void ldsm_x2(uint32_t b[2], uint32_t addr) {
    asm volatile("ldmatrix.sync.aligned.m8n8.x2.shared.b16 {%0,%1}, [%2];"
                 : "=r"(b[0]), "=r"(b[1]) : "r"(addr));
}
__device__ __forceinline__ void ldsm_x2t(uint32_t b[2], uint32_t addr) {
    asm volatile("ldmatrix.sync.aligned.m8n8.x2.trans.shared.b16 {%0,%1}, [%2];"
                 : "=r"(b[0]), "=r"(b[1]) : "r"(addr));
}
__device__ __forceinline__ void mma_bf16(float acc[4], const uint32_t a[4],
                                         const uint32_t b[2]) {
    asm("mma.sync.aligned.m16n8k16.row.col.f32.bf16.bf16.f32 "
        "{%0,%1,%2,%3},{%4,%5,%6,%7},{%8,%9},{%0,%1,%2,%3};"
        : "+f"(acc[0]), "+f"(acc[1]), "+f"(acc[2]), "+f"(acc[3])
        : "r"(a[0]), "r"(a[1]), "r"(a[2]), "r"(a[3]), "r"(b[0]), "r"(b[1]));
}

// ===========================================================================
// mma.sync bf16 GEMM core, register double-buffer (qkv & proj)
//   MODE 0: KC bf16; MODE 1: KC fp32; MODE 2: KT bf16; MODE 3: KT fp32 + GN
// ===========================================================================
template <int MODE>
__device__ __forceinline__ void ldg_bf(const void* gp, int ld, int k0, int tid,
                                       uint4 r[2],
                                       const float* __restrict__ sc,
                                       const float* __restrict__ sb) {
    if (MODE == 0) {
        const __nv_bfloat16* g = (const __nv_bfloat16*)gp;
        int x = tid >> 1, kq = (tid & 1) << 4;
        const uint4* p = (const uint4*)(g + (size_t)x * ld + k0 + kq);
        r[0] = p[0];
        r[1] = p[1];
    } else if (MODE == 1) {
        const float* g = (const float*)gp;
        int x = tid >> 1, kq = (tid & 1) << 4;
        const float4* p = (const float4*)(g + (size_t)x * ld + k0 + kq);
        float4 f0 = p[0], f1 = p[1], f2 = p[2], f3 = p[3];
        r[0].x = packbf(f0.x, f0.y); r[0].y = packbf(f0.z, f0.w);
        r[0].z = packbf(f1.x, f1.y); r[0].w = packbf(f1.z, f1.w);
        r[1].x = packbf(f2.x, f2.y); r[1].y = packbf(f2.z, f2.w);
        r[1].z = packbf(f3.x, f3.y); r[1].w = packbf(f3.z, f3.w);
    } else if (MODE == 2) {
        const __nv_bfloat16* g = (const __nv_bfloat16*)gp;
        int kw = tid >> 5, x4 = (tid & 31) << 2;
        const __nv_bfloat16* base = g + (size_t)(k0 + 2 * kw) * ld + x4;
        uint2 u0 = *(const uint2*)base;
        uint2 u1 = *(const uint2*)(base + ld);
        uint2 u2 = *(const uint2*)(base + (size_t)16 * ld);
        uint2 u3 = *(const uint2*)(base + (size_t)17 * ld);
        r[0].x = u0.x; r[0].y = u0.y; r[0].z = u1.x; r[0].w = u1.y;
        r[1].x = u2.x; r[1].y = u2.y; r[1].z = u3.x; r[1].w = u3.y;
    } else {
        const float* g = (const float*)gp;
        int kw = tid >> 5, x4 = (tid & 31) << 2;
        int kr = k0 + 2 * kw;
        const float* base = g + (size_t)kr * ld + x4;
        float4 f0 = *(const float4*)base;
        float4 f1 = *(const float4*)(base + ld);
        float4 f2 = *(const float4*)(base + (size_t)16 * ld);
        float4 f3 = *(const float4*)(base + (size_t)17 * ld);
        float s0 = sc[kr],      o0 = sb[kr];
        float s1 = sc[kr + 1],  o1 = sb[kr + 1];
        float s2 = sc[kr + 16], o2 = sb[kr + 16];
        float s3 = sc[kr + 17], o3 = sb[kr + 17];
        r[0].x = packbf(f0.x * s0 + o0, f0.y * s0 + o0);
        r[0].y = packbf(f0.z * s0 + o0, f0.w * s0 + o0);
        r[0].z = packbf(f1.x * s1 + o1, f1.y * s1 + o1);
        r[0].w = packbf(f1.z * s1 + o1, f1.w * s1 + o1);
        r[1].x = packbf(f2.x * s2 + o2, f2.y * s2 + o2);
        r[1].y = packbf(f2.z * s2 + o2, f2.w * s2 + o2);
        r[1].z = packbf(f3.x * s3 + o3, f3.y * s3 + o3);
        r[1].w = packbf(f3.z * s3 + o3, f3.w * s3 + o3);
    }
}

template <int MODE>
__device__ __forceinline__ void sts_bf(uint32_t* s, int tid, const uint4 r[2]) {
    if (MODE >= 2) {
        int kw = tid >> 5, xw = (tid & 31) * 2;
        *(uint2*)(s + (2 * kw) * KTS + xw)      = make_uint2(r[0].x, r[0].y);
        *(uint2*)(s + (2 * kw + 1) * KTS + xw)  = make_uint2(r[0].z, r[0].w);
        *(uint2*)(s + (2 * kw + 16) * KTS + xw) = make_uint2(r[1].x, r[1].y);
        *(uint2*)(s + (2 * kw + 17) * KTS + xw) = make_uint2(r[1].z, r[1].w);
    } else {
        int x = tid >> 1, kq8 = (tid & 1) << 3;
        *(uint4*)(s + x * BSKC + kq8)     = r[0];
        *(uint4*)(s + x * BSKC + kq8 + 4) = r[1];
    }
}

template <int AM, int BM>
__device__ __forceinline__ void gemm_bf(const void* Ag, int lda,
                                        const void* Bg, int ldb,
                                        int K, float acc[4][4][4],
                                        const float* bsc = nullptr,
                                        const float* bsb = nullptr) {
    __shared__ uint32_t sm[2][2][BSMW];
    const int tid = threadIdx.x;
    const int warp = tid >> 5, lane = tid & 31;
    const int mBase = (warp >> 2) * 64;
    const int nBase = (warp & 3) * 32;
    const int l8 = lane & 7, lb3 = (lane >> 3) & 1, lb4 = (lane >> 4) & 1;
    const int lm = lane & 15, lm8 = lm & 7, lmb3 = (lm >> 3) & 1;

    const uint32_t smAddr = (uint32_t)__cvta_generic_to_shared(&sm[0][0][0]);

    uint4 ra[2], rb[2];
    ldg_bf<AM>(Ag, lda, 0, tid, ra, nullptr, nullptr);
    ldg_bf<BM>(Bg, ldb, 0, tid, rb, bsc, bsb);
    sts_bf<AM>(sm[0][0], tid, ra);
    sts_bf<BM>(sm[0][1], tid, rb);
    __syncthreads();

    const int nk = K >> 5;
    for (int ik = 0; ik < nk; ik++) {
        const int cur = ik & 1;
        if (ik + 1 < nk) {
            ldg_bf<AM>(Ag, lda, (ik + 1) << 5, tid, ra, nullptr, nullptr);
            ldg_bf<BM>(Bg, ldb, (ik + 1) << 5, tid, rb, bsc, bsb);
        }
        const uint32_t baseA = smAddr + (uint32_t)(cur * 2 + 0) * (BSMW * 4);
        const uint32_t baseB = smAddr + (uint32_t)(cur * 2 + 1) * (BSMW * 4);
#pragma unroll
        for (int kks = 0; kks < 2; kks++) {
            uint32_t a[4][4], b[4][2];
#pragma unroll
            for (int i = 0; i < 4; i++) {
                uint32_t ad;
                if (AM < 2)
                    ad = baseA + (uint32_t)(((mBase + i * 16 + l8 + lb3 * 8) * BSKC
                                             + kks * 8 + lb4 * 4) << 2);
                else
                    ad = baseA + (uint32_t)(((kks * 16 + l8 + lb4 * 8) * KTS) << 2)
                               + (uint32_t)((mBase + i * 16 + lb3 * 8) << 1);
                if (AM < 2) ldsm_x4(a[i], ad); else ldsm_x4t(a[i], ad);
            }
#pragma unroll
            for (int j = 0; j < 4; j++) {
                uint32_t bd;
                if (BM < 2)
                    bd = baseB + (uint32_t)(((nBase + j * 8 + lm8) * BSKC
                                             + kks * 8 + lmb3 * 4) << 2);
                else
                    bd = baseB + (uint32_t)(((kks * 16 + lm8 + lmb3 * 8) * KTS) << 2)
                               + (uint32_t)((nBase + j * 8) << 1);
                if (BM < 2) ldsm_x2(b[j], bd); else ldsm_x2t(b[j], bd);
            }
#pragma unroll
            for (int i = 0; i < 4; i++)
#pragma unroll
                for (int j = 0; j < 4; j++)
                    mma_bf16(acc[i][j], a[i], b[j]);
        }
        if (ik + 1 < nk) {
            sts_bf<AM>(sm[cur ^ 1][0], tid, ra);
            sts_bf<BM>(sm[cur ^ 1][1], tid, rb);
        }
        __syncthreads();
    }
}

// ===========================================================================
// cp.async 4-stage pipelined GEMM core, KC variant (k_av)
// B fragments via x4 pair-loads; single barrier per K-chunk.
// ===========================================================================
#define CATILE 20480
#define CA_SMEM (4 * CATILE)

__device__ __forceinline__ void ca_load(uint32_t sdst, const __nv_bfloat16* g,
                                        int ld, int tid) {
    int x = tid >> 2;          // 0..63
    int q = tid & 3;
    const char* gp = (const char*)g;
#pragma unroll
    for (int h = 0; h < 2; h++) {
        int row = x + h * 64;
        asm volatile("cp.async.cg.shared.global [%0], [%1], 16;"
                     :: "r"(sdst + row * 80 + q * 16),
                        "l"(gp + (size_t)row * ld * 2 + q * 16));
    }
}

__device__ __forceinline__ void gemm_ca(const __nv_bfloat16* __restrict__ Ag, int lda,
                                        const __nv_bfloat16* __restrict__ Bg, int ldb,
                                        int K, float acc[4][4][4], uint32_t sbase) {
    const int tid = threadIdx.x;
    const int warp = tid >> 5, lane = tid & 31;
    const int mBase = (warp >> 2) * 64;
    const int nBase = (warp & 3) * 32;
    const int l8 = lane & 7, lb3 = (lane >> 3) & 1, lb4 = (lane >> 4) & 1;

    const int nk = K >> 5;
#pragma unroll
    for (int s = 0; s < 3; s++) {
        if (s < nk) {
            ca_load(sbase + s * CATILE,         Ag + s * 32, lda, tid);
            ca_load(sbase + s * CATILE + 10240, Bg + s * 32, ldb, tid);
        }
        asm volatile("cp.async.commit_group;");
    }
    for (int ik = 0; ik < nk; ik++) {
        asm volatile("cp.async.wait_group 2;");
        __syncthreads();
        const uint32_t baseA = sbase + (ik & 3) * CATILE;
        const uint32_t baseB = baseA + 10240;
#pragma unroll
        for (int kks = 0; kks < 2; kks++) {
            uint32_t a[4][4], b[4][2];
#pragma unroll
            for (int i = 0; i < 4; i++)
                ldsm_x4(a[i], baseA + (uint32_t)(((mBase + i * 16 + l8 + lb3 * 8) * BSKC
                                                  + kks * 8 + lb4 * 4) << 2));
#pragma unroll
            for (int j2 = 0; j2 < 2; j2++) {
                uint32_t bb[4];
                ldsm_x4(bb, baseB + (uint32_t)(((nBase + j2 * 16 + l8 + lb3 * 8) * BSKC
                                                + kks * 8 + lb4 * 4) << 2));
                b[j2 * 2][0]     = bb[0];
                b[j2 * 2 + 1][0] = bb[1];
                b[j2 * 2][1]     = bb[2];
                b[j2 * 2 + 1][1] = bb[3];
            }
#pragma unroll
            for (int i = 0; i < 4; i++)
#pragma unroll
                for (int j = 0; j < 4; j++)
                    mma_bf16(acc[i][j], a[i], b[j]);
        }
        if (ik + 3 < nk) {
            ca_load(sbase + ((ik + 3) & 3) * CATILE,         Ag + (ik + 3) * 32, lda, tid);
            ca_load(sbase + ((ik + 3) & 3) * CATILE + 10240, Bg + (ik + 3) * 32, ldb, tid);
        }
        asm volatile("cp.async.commit_group;");
    }
}

// ===========================================================================
// cp.async 4-stage pipelined GEMM core, KT variant (k_scores)
// B fragments via x4t pair-loads; single barrier per K-chunk.
// ===========================================================================
#define CAKT_TILE 17408
#define CAKT_SMEM (4 * CAKT_TILE)

__device__ __forceinline__ void ca_load_kt(uint32_t sdst, const __nv_bfloat16* g,
                                           int ld, int tid) {
    int row = tid >> 3;        // k-row 0..31
    int seg = tid & 7;         // 16B segment
    const char* gp = (const char*)g + (size_t)row * ld * 2;
    uint32_t sd = sdst + (uint32_t)row * (KTS * 4);
#pragma unroll
    for (int h = 0; h < 2; h++) {
        int sg = seg + h * 8;
        asm volatile("cp.async.cg.shared.global [%0], [%1], 16;"
                     :: "r"(sd + sg * 16), "l"(gp + sg * 16));
    }
}

__device__ __forceinline__ void gemm_ca_kt(const __nv_bfloat16* __restrict__ Ag,
                                           const __nv_bfloat16* __restrict__ Bg,
                                           int ld, int K, float acc[4][4][4],
                                           uint32_t sbase) {
    const int tid = threadIdx.x;
    const int warp = tid >> 5, lane = tid & 31;
    const int mBase = (warp >> 2) * 64;
    const int nBase = (warp & 3) * 32;
    const int l8 = lane & 7, lb3 = (lane >> 3) & 1, lb4 = (lane >> 4) & 1;

    const int nk = K >> 5;
#pragma unroll
    for (int s = 0; s < 3; s++) {
        if (s < nk) {
            ca_load_kt(sbase + s * CAKT_TILE,        Ag + (size_t)s * 32 * ld, ld, tid);
            ca_load_kt(sbase + s * CAKT_TILE + 8704, Bg + (size_t)s * 32 * ld, ld, tid);
        }
        asm volatile("cp.async.commit_group;");
    }
    for (int ik = 0; ik < nk; ik++) {
        asm volatile("cp.async.wait_group 2;");
        __syncthreads();
        const uint32_t baseA = sbase + (ik & 3) * CAKT_TILE;
        const uint32_t baseB = baseA + 8704;
#pragma unroll
        for (int kks = 0; kks < 2; kks++) {
            uint32_t a[4][4], b[4][2];
#pragma unroll
            for (int i = 0; i < 4; i++)
                ldsm_x4t(a[i], baseA + (uint32_t)(((kks * 16 + l8 + lb4 * 8) * KTS) << 2)
                               + (uint32_t)((mBase + i * 16 + lb3 * 8) << 1));
#pragma unroll
            for (int j2 = 0; j2 < 2; j2++) {
                uint32_t bb[4];
                ldsm_x4t(bb, baseB + (uint32_t)(((kks * 16 + l8 + lb4 * 8) * KTS) << 2)
                               + (uint32_t)((nBase + j2 * 16 + lb3 * 8) << 1));
                b[j2 * 2][0]     = bb[0];
                b[j2 * 2 + 1][0] = bb[1];
                b[j2 * 2][1]     = bb[2];
                b[j2 * 2 + 1][1] = bb[3];
            }
#pragma unroll
            for (int i = 0; i < 4; i++)
#pragma unroll
                for (int j = 0; j < 4; j++)
                    mma_bf16(acc[i][j], a[i], b[j]);
        }
        if (ik + 3 < nk) {
            ca_load_kt(sbase + ((ik + 3) & 3) * CAKT_TILE,
                       Ag + (size_t)(ik + 3) * 32 * ld, ld, tid);
            ca_load_kt(sbase + ((ik + 3) & 3) * CAKT_TILE + 8704,
                       Bg + (size_t)(ik + 3) * 32 * ld, ld, tid);
        }
        asm volatile("cp.async.commit_group;");
    }
}

// ---------------------------------------------------------------------------
// QKV: q,k,v written [C][T] channel-major
// ---------------------------------------------------------------------------
__global__ void __launch_bounds__(256, 2) k_qkv(const float* __restrict__ W,
                                                const float* __restrict__ bias,
                                                const float* __restrict__ x) {
    int n  = blockIdx.z;
    int m0 = blockIdx.y * 128;
    int t0 = blockIdx.x * 128;
    float acc[4][4][4] = {};
    gemm_bf<1, 3>(W + (size_t)m0 * C, C,
                  x + (size_t)n * C * T + t0, T, C, acc,
                  g_sc + n * C, g_sb + n * C);

    int which = m0 >> 9;
    __nv_bfloat16* dst =
        (which == 0 ? g_q : which == 1 ? g_k : g_v) + (size_t)n * C * T;
    int dbase = m0 & (C - 1);
    const int warp = threadIdx.x >> 5, lane = threadIdx.x & 31;
    const int g = lane >> 2, tg = lane & 3;
    const int mB = (warp >> 2) * 64, nB = (warp & 3) * 32;
#pragma unroll
    for (int i = 0; i < 4; i++) {
        int r = mB + i * 16 + g;
        float bv0 = bias[m0 + r];
        float bv1 = bias[m0 + r + 8];
#pragma unroll
        for (int j = 0; j < 4; j++) {
            int col = t0 + nB + j * 8 + tg * 2;
            uint32_t w0 = packbf(acc[i][j][0] + bv0, acc[i][j][1] + bv0);
            uint32_t w1 = packbf(acc[i][j][2] + bv1, acc[i][j][3] + bv1);
            *(uint32_t*)&dst[(size_t)(dbase + r) * T + col]     = w0;
            *(uint32_t*)&dst[(size_t)(dbase + r + 8) * T + col] = w1;
        }
    }
}

// ---------------------------------------------------------------------------
// scores: p[t][s] = exp(scale * q.k); per-(row, s-tile) sums -> g_lp
// ---------------------------------------------------------------------------
__global__ void __launch_bounds__(256, 2) k_scores() {
    extern __shared__ char smraw[];
    uint32_t sbase = (uint32_t)__cvta_generic_to_shared(smraw);
    int n  = blockIdx.z;
    int t0 = blockIdx.y * 128;
    int s0 = blockIdx.x * 128;
    float acc[4][4][4] = {};
    gemm_ca_kt(g_q + (size_t)n * C * T + t0,
               g_k + (size_t)n * C * T + s0, T, C, acc, sbase);

    const float scale = 0.04419417382415922f;  // 512^-0.5
    __nv_bfloat16* dst = g_p + (size_t)n * T * T;
    __shared__ float sm_l[128][4];
    const int warp = threadIdx.x >> 5, lane = threadIdx.x & 31;
    const int g = lane >> 2, tg = lane & 3;
    const int mB = (warp >> 2) * 64, nB = (warp & 3) * 32;
#pragma unroll
    for (int i = 0; i < 4; i++) {
        int r = t0 + mB + i * 16 + g;
        float ps0 = 0.f, ps1 = 0.f;
#pragma unroll
        for (int j = 0; j < 4; j++) {
            int col = s0 + nB + j * 8 + tg * 2;
            float e0 = __expf(acc[i][j][0] * scale);
            float e1 = __expf(acc[i][j][1] * scale);
            float e2 = __expf(acc[i][j][2] * scale);
            float e3 = __expf(acc[i][j][3] * scale);
            ps0 += e0 + e1;
            ps1 += e2 + e3;
            *(uint32_t*)&dst[(size_t)r * T + col]       = packbf(e0, e1);
            *(uint32_t*)&dst[(size_t)(r + 8) * T + col] = packbf(e2, e3);
        }
        ps0 += __shfl_xor_sync(0xffffffffu, ps0, 1);
        ps0 += __shfl_xor_sync(0xffffffffu, ps0, 2);
        ps1 += __shfl_xor_sync(0xffffffffu, ps1, 1);
        ps1 += __shfl_xor_sync(0xffffffffu, ps1, 2);
        if (tg == 0) {
            sm_l[mB + i * 16 + g][warp & 3]     = ps0;
            sm_l[mB + i * 16 + g + 8][warp & 3] = ps1;
        }
    }
    __syncthreads();
    if (threadIdx.x < 128) {
        float l = sm_l[threadIdx.x][0] + sm_l[threadIdx.x][1]
                + sm_l[threadIdx.x][2] + sm_l[threadIdx.x][3];
        g_lp[((size_t)n * 32 + blockIdx.x) * T + t0 + threadIdx.x] = l;
    }
}

// ---------------------------------------------------------------------------
// inv row sum (fixed order, deterministic)
// ---------------------------------------------------------------------------
__global__ void __launch_bounds__(256) k_lsum() {
    int idx = blockIdx.x * 256 + threadIdx.x;
    int n = idx >> 12, t = idx & (T - 1);
    const float* lp = g_lp + (size_t)n * 32 * T + t;
    float l = 0.f;
#pragma unroll
    for (int i = 0; i < 32; i++) l += lp[(size_t)i * T];
    g_li[idx] = 1.f / l;
}

// ---------------------------------------------------------------------------
// AV: o[t][c] = inv_l[t] * sum_s p[t][s] * v[c][s]
// ---------------------------------------------------------------------------
__global__ void __launch_bounds__(256, 2) k_av() {
    extern __shared__ char smraw[];
    uint32_t sbase = (uint32_t)__cvta_generic_to_shared(smraw);
    int n  = blockIdx.z;
    int t0 = blockIdx.y * 128;
    int c0 = blockIdx.x * 128;
    float acc[4][4][4] = {};
    gemm_ca(g_p + ((size_t)n * T + t0) * T, T,
            g_v + ((size_t)n * C + c0) * T, T, T, acc, sbase);

    __nv_bfloat16* dst = g_o + (size_t)n * T * C;
    const int warp = threadIdx.x >> 5, lane = threadIdx.x & 31;
    const int g = lane >> 2, tg = lane & 3;
    const int mB = (warp >> 2) * 64, nB = (warp & 3) * 32;
#pragma unroll
    for (int i = 0; i < 4; i++) {
        int r = t0 + mB + i * 16 + g;
        float inv0 = g_li[n * T + r];
        float inv1 = g_li[n * T + r + 8];
#pragma unroll
        for (int j = 0; j < 4; j++) {
            int col = c0 + nB + j * 8 + tg * 2;
            uint32_t w0 = packbf(acc[i][j][0] * inv0, acc[i][j][1] * inv0);
            uint32_t w1 = packbf(acc[i][j][2] * inv1, acc[i][j][3] * inv1);
            *(uint32_t*)&dst[(size_t)r * C + col]       = w0;
            *(uint32_t*)&dst[(size_t)(r + 8) * C + col] = w1;
        }
    }
}

// ---------------------------------------------------------------------------
// proj: out[n][d][t] = proj_w[d][:] . o[t][:] + proj_b[d] + x[n][d][t]
// ---------------------------------------------------------------------------
__global__ void __launch_bounds__(256, 2) k_proj(const float* __restrict__ W,
                                                 const float* __restrict__ bias,
                                                 const float* __restrict__ x,
                                                 float* __restrict__ out) {
    int n  = blockIdx.z;
    int d0 = blockIdx.y * 128;
    int t0 = blockIdx.x * 128;
    float acc[4][4][4] = {};
    gemm_bf<1, 0>(W + (size_t)d0 * C, C,
                  g_o + (size_t)n * T * C + (size_t)t0 * C, C, C, acc);

    const int warp = threadIdx.x >> 5, lane = threadIdx.x & 31;
    const int g = lane >> 2, tg = lane & 3;
    const int mB = (warp >> 2) * 64, nB = (warp & 3) * 32;
#pragma unroll
    for (int i = 0; i < 4; i++) {
        int d = d0 + mB + i * 16 + g;
        float bv0 = bias[d];
        float bv1 = bias[d + 8];
#pragma unroll
        for (int j = 0; j < 4; j++) {
            int col = t0 + nB + j * 8 + tg * 2;
            size_t base0 = ((size_t)n * C + d) * T + col;
            size_t base1 = ((size_t)n * C + d + 8) * T + col;
            float2 x0 = *(const float2*)&x[base0];
            float2 x1 = *(const float2*)&x[base1];
            float2 v0 = { acc[i][j][0] + bv0 + x0.x, acc[i][j][1] + bv0 + x0.y };
            float2 v1 = { acc[i][j][2] + bv1 + x1.x, acc[i][j][3] + bv1 + x1.y };
            *(float2*)&out[base0] = v0;
            *(float2*)&out[base1] = v1;
        }
    }
}

// ---------------------------------------------------------------------------
extern "C" void kernel_launch(void* const* d_in, const int* in_sizes, int n_in,
                              void* d_out, int out_size) {
    const float* x      = (const float*)d_in[0];
    const float* gn_w   = (const float*)d_in[1];
    const float* gn_b   = (const float*)d_in[2];
    const float* qkv_w  = (const float*)d_in[3];
    const float* qkv_b  = (const float*)d_in[4];
    const float* proj_w = (const float*)d_in[5];
    const float* proj_b = (const float*)d_in[6];
    float* out = (float*)d_out;

    cudaFuncSetAttribute(k_av,     cudaFuncAttributeMaxDynamicSharedMemorySize, CA_SMEM);
    cudaFuncSetAttribute(k_scores, cudaFuncAttributeMaxDynamicSharedMemorySize, CAKT_SMEM);

    gn_stats<<<NB * GROUPS, 256>>>(x, gn_w, gn_b);
    k_qkv   <<<dim3(T / 128, (3 * C) / 128, NB), 256>>>(qkv_w, qkv_b, x);
    k_scores<<<dim3(T / 128, T / 128, NB), 256, CAKT_SMEM>>>();
    k_lsum  <<<NB * T / 256, 256>>>();
    k_av    <<<dim3(C / 128, T / 128, NB), 256, CA_SMEM>>>();
    k_proj  <<<dim3(T / 128, C / 128, NB), 256>>>(proj_w, proj_b, x, out);
}

// round 16
// speedup vs baseline: 1.0550x; 1.0550x over previous
#include <cuda_runtime.h>
#include <cuda_bf16.h>
#include <cstdint>

#define NB 8
#define C 512
#define T 4096
#define GROUPS 32
#define CPG (C / GROUPS)      // 16
#define GSZ (CPG * T)         // 65536 elements per group

// Scratch (device globals; no allocations allowed)
__device__ float g_sc[NB * C];                         // GN scale  per (n,c)
__device__ float g_sb[NB * C];                         // GN shift  per (n,c)
__device__ __nv_bfloat16 g_wq[3 * C * C];              // qkv_w bf16
__device__ __nv_bfloat16 g_wp[C * C];                  // proj_w bf16
__device__ __nv_bfloat16 g_q[(size_t)NB * C * T];      // [N][C][T]
__device__ __nv_bfloat16 g_k[(size_t)NB * C * T];      // [N][C][T]
__device__ __nv_bfloat16 g_v[(size_t)NB * C * T];      // [N][C][T]
__device__ __nv_bfloat16 g_o[(size_t)NB * T * C];      // [N][T][C]
__device__ __nv_bfloat16 g_p[(size_t)NB * T * T];      // [N][T][T] bf16 exp(S)
__device__ float g_lp[(size_t)NB * 32 * T];            // partial row sums
__device__ float g_li[NB * T];                         // 1 / row sum

__device__ __forceinline__ uint32_t packbf(float lo, float hi) {
    __nv_bfloat162 h = __float22bfloat162_rn(make_float2(lo, hi));
    return *(uint32_t*)&h;
}

// ---------------------------------------------------------------------------
// Weight pre-conversion: fp32 -> bf16 once per launch
// ---------------------------------------------------------------------------
#define NQ4 (3 * C * C / 4)   // 196608 float4s in qkv_w
#define NP4 (C * C / 4)       // 65536  float4s in proj_w
__global__ void __launch_bounds__(256) k_cvt(const float* __restrict__ qw,
                                             const float* __restrict__ pw) {
    int idx = blockIdx.x * 256 + threadIdx.x;
    float4 v;
    uint2* dst;
    if (idx < NQ4) {
        v = ((const float4*)qw)[idx];
        dst = (uint2*)g_wq + idx;
    } else {
        v = ((const float4*)pw)[idx - NQ4];
        dst = (uint2*)g_wp + (idx - NQ4);
    }
    *dst = make_uint2(packbf(v.x, v.y), packbf(v.z, v.w));
}

// ---------------------------------------------------------------------------
// GroupNorm stats: one block per (n, group); writes per-channel scale/shift
// ---------------------------------------------------------------------------
__global__ void __launch_bounds__(256) gn_stats(const float* __restrict__ x,
                                                const float* __restrict__ w,
                                                const float* __restrict__ b) {
    int n = blockIdx.x >> 5;
    int g = blockIdx.x & 31;
    const float4* xp = (const float4*)(x + ((size_t)n * C + g * CPG) * T);
    const int NV = GSZ / 4;

    float s = 0.f, s2 = 0.f;
    for (int i = threadIdx.x; i < NV; i += 256) {
        float4 v = xp[i];
        s  += v.x + v.y + v.z + v.w;
        s2 += v.x * v.x + v.y * v.y + v.z * v.z + v.w * v.w;
    }
    __shared__ float rs[32], rs2[32];
    int lid = threadIdx.x & 31, wid = threadIdx.x >> 5;
#pragma unroll
    for (int o = 16; o; o >>= 1) {
        s  += __shfl_xor_sync(0xffffffffu, s, o);
        s2 += __shfl_xor_sync(0xffffffffu, s2, o);
    }
    if (lid == 0) { rs[wid] = s; rs2[wid] = s2; }
    __syncthreads();
    if (wid == 0) {
        s  = (lid < 8) ? rs[lid]  : 0.f;
        s2 = (lid < 8) ? rs2[lid] : 0.f;
#pragma unroll
        for (int o = 4; o; o >>= 1) {
            s  += __shfl_xor_sync(0xffffffffu, s, o);
            s2 += __shfl_xor_sync(0xffffffffu, s2, o);
        }
        if (lid == 0) { rs[0] = s; rs2[0] = s2; }
    }
    __syncthreads();
    float mean = rs[0] * (1.f / GSZ);
    float var  = rs2[0] * (1.f / GSZ) - mean * mean;
    float inv  = rsqrtf(var + 1e-5f);

    if (threadIdx.x < CPG) {
        int c = g * CPG + threadIdx.x;
        float scv = w[c] * inv;
        g_sc[n * C + c] = scv;
        g_sb[n * C + c] = b[c] - mean * scv;
    }
}

// ===========================================================================
// Common helpers
// ===========================================================================
#define BSKC 20
#define KTS  68
#define BSMW 2560

__device__ __forceinline__ void ldsm_x4(uint32_t a[4], uint32_t addr) {
    asm volatile("ldmatrix.sync.aligned.m8n8.x4.shared.b16 {%0,%1,%2,%3}, [%4];"
                 : "=r"(a[0]), "=r"(a[1]), "=r"(a[2]), "=r"(a[3]) : "r"(addr));
}
__device__ __forceinline__ void ldsm_x4t(uint32_t a[4], uint32_t addr) {
    asm volatile("ldmatrix.sync.aligned.m8n8.x4.trans.shared.b16 {%0,%1,%2,%3}, [%4];"
                 : "=r"(a[0]), "=r"(a[1]), "=r"(a[2]), "=r"(a[3]) : "r"(addr));
}
__device__ __forceinline__ void ldsm_x2(uint32_t b[2], uint32_t addr) {
    asm volatile("ldmatrix.sync.aligned.m8n8.x2.shared.b16 {%0,%1}, [%2];"
                 : "=r"(b[0]), "=r"(b[1]) : "r"(addr));
}
__device__ __forceinline__ void ldsm_x2t(uint32_t b[2], uint32_t addr) {
    asm volatile("ldmatrix.sync.aligned.m8n8.x2.trans.shared.b16 {%0,%1}, [%2];"
                 : "=r"(b[0]), "=r"(b[1]) : "r"(addr));
}
__device__ __forceinline__ void mma_bf16(float acc[4], const uint32_t a[4],
                                         const uint32_t b[2]) {
    asm("mma.sync.aligned.m16n8k16.row.col.f32.bf16.bf16.f32 "
        "{%0,%1,%2,%3},{%4,%5,%6,%7},{%8,%9},{%0,%1,%2,%3};"
        : "+f"(acc[0]), "+f"(acc[1]), "+f"(acc[2]), "+f"(acc[3])
        : "r"(a[0]), "r"(a[1]), "r"(a[2]), "r"(a[3]), "r"(b[0]), "r"(b[1]));
}

// ===========================================================================
// mma.sync bf16 GEMM core, register double-buffer (qkv & proj)
//   MODE 0: KC bf16; MODE 1: KC fp32; MODE 2: KT bf16; MODE 3: KT fp32 + GN
// ===========================================================================
template <int MODE>
__device__ __forceinline__ void ldg_bf(const void* gp, int ld, int k0, int tid,
                                       uint4 r[2],
                                       const float* __restrict__ sc,
                                       const float* __restrict__ sb) {
    if (MODE == 0) {
        const __nv_bfloat16* g = (const __nv_bfloat16*)gp;
        int x = tid >> 1, kq = (tid & 1) << 4;
        const uint4* p = (const uint4*)(g + (size_t)x * ld + k0 + kq);
        r[0] = p[0];
        r[1] = p[1];
    } else if (MODE == 1) {
        const float* g = (const float*)gp;
        int x = tid >> 1, kq = (tid & 1) << 4;
        const float4* p = (const float4*)(g + (size_t)x * ld + k0 + kq);
        float4 f0 = p[0], f1 = p[1], f2 = p[2], f3 = p[3];
        r[0].x = packbf(f0.x, f0.y); r[0].y = packbf(f0.z, f0.w);
        r[0].z = packbf(f1.x, f1.y); r[0].w = packbf(f1.z, f1.w);
        r[1].x = packbf(f2.x, f2.y); r[1].y = packbf(f2.z, f2.w);
        r[1].z = packbf(f3.x, f3.y); r[1].w = packbf(f3.z, f3.w);
    } else if (MODE == 2) {
        const __nv_bfloat16* g = (const __nv_bfloat16*)gp;
        int kw = tid >> 5, x4 = (tid & 31) << 2;
        const __nv_bfloat16* base = g + (size_t)(k0 + 2 * kw) * ld + x4;
        uint2 u0 = *(const uint2*)base;
        uint2 u1 = *(const uint2*)(base + ld);
        uint2 u2 = *(const uint2*)(base + (size_t)16 * ld);
        uint2 u3 = *(const uint2*)(base + (size_t)17 * ld);
        r[0].x = u0.x; r[0].y = u0.y; r[0].z = u1.x; r[0].w = u1.y;
        r[1].x = u2.x; r[1].y = u2.y; r[1].z = u3.x; r[1].w = u3.y;
    } else {
        const float* g = (const float*)gp;
        int kw = tid >> 5, x4 = (tid & 31) << 2;
        int kr = k0 + 2 * kw;
        const float* base = g + (size_t)kr * ld + x4;
        float4 f0 = *(const float4*)base;
        float4 f1 = *(const float4*)(base + ld);
        float4 f2 = *(const float4*)(base + (size_t)16 * ld);
        float4 f3 = *(const float4*)(base + (size_t)17 * ld);
        float s0 = sc[kr],      o0 = sb[kr];
        float s1 = sc[kr + 1],  o1 = sb[kr + 1];
        float s2 = sc[kr + 16], o2 = sb[kr + 16];
        float s3 = sc[kr + 17], o3 = sb[kr + 17];
        r[0].x = packbf(f0.x * s0 + o0, f0.y * s0 + o0);
        r[0].y = packbf(f0.z * s0 + o0, f0.w * s0 + o0);
        r[0].z = packbf(f1.x * s1 + o1, f1.y * s1 + o1);
        r[0].w = packbf(f1.z * s1 + o1, f1.w * s1 + o1);
        r[1].x = packbf(f2.x * s2 + o2, f2.y * s2 + o2);
        r[1].y = packbf(f2.z * s2 + o2, f2.w * s2 + o2);
        r[1].z = packbf(f3.x * s3 + o3, f3.y * s3 + o3);
        r[1].w = packbf(f3.z * s3 + o3, f3.w * s3 + o3);
    }
}

template <int MODE>
__device__ __forceinline__ void sts_bf(uint32_t* s, int tid, const uint4 r[2]) {
    if (MODE >= 2) {
        int kw = tid >> 5, xw = (tid & 31) * 2;
        *(uint2*)(s + (2 * kw) * KTS + xw)      = make_uint2(r[0].x, r[0].y);
        *(uint2*)(s + (2 * kw + 1) * KTS + xw)  = make_uint2(r[0].z, r[0].w);
        *(uint2*)(s + (2 * kw + 16) * KTS + xw) = make_uint2(r[1].x, r[1].y);
        *(uint2*)(s + (2 * kw + 17) * KTS + xw) = make_uint2(r[1].z, r[1].w);
    } else {
        int x = tid >> 1, kq8 = (tid & 1) << 3;
        *(uint4*)(s + x * BSKC + kq8)     = r[0];
        *(uint4*)(s + x * BSKC + kq8 + 4) = r[1];
    }
}

template <int AM, int BM>
__device__ __forceinline__ void gemm_bf(const void* Ag, int lda,
                                        const void* Bg, int ldb,
                                        int K, float acc[4][4][4],
                                        const float* bsc = nullptr,
                                        const float* bsb = nullptr) {
    __shared__ uint32_t sm[2][2][BSMW];
    const int tid = threadIdx.x;
    const int warp = tid >> 5, lane = tid & 31;
    const int mBase = (warp >> 2) * 64;
    const int nBase = (warp & 3) * 32;
    const int l8 = lane & 7, lb3 = (lane >> 3) & 1, lb4 = (lane >> 4) & 1;
    const int lm = lane & 15, lm8 = lm & 7, lmb3 = (lm >> 3) & 1;

    const uint32_t smAddr = (uint32_t)__cvta_generic_to_shared(&sm[0][0][0]);

    uint4 ra[2], rb[2];
    ldg_bf<AM>(Ag, lda, 0, tid, ra, nullptr, nullptr);
    ldg_bf<BM>(Bg, ldb, 0, tid, rb, bsc, bsb);
    sts_bf<AM>(sm[0][0], tid, ra);
    sts_bf<BM>(sm[0][1], tid, rb);
    __syncthreads();

    const int nk = K >> 5;
    for (int ik = 0; ik < nk; ik++) {
        const int cur = ik & 1;
        if (ik + 1 < nk) {
            ldg_bf<AM>(Ag, lda, (ik + 1) << 5, tid, ra, nullptr, nullptr);
            ldg_bf<BM>(Bg, ldb, (ik + 1) << 5, tid, rb, bsc, bsb);
        }
        const uint32_t baseA = smAddr + (uint32_t)(cur * 2 + 0) * (BSMW * 4);
        const uint32_t baseB = smAddr + (uint32_t)(cur * 2 + 1) * (BSMW * 4);
#pragma unroll
        for (int kks = 0; kks < 2; kks++) {
            uint32_t a[4][4], b[4][2];
#pragma unroll
            for (int i = 0; i < 4; i++) {
                uint32_t ad;
                if (AM < 2)
                    ad = baseA + (uint32_t)(((mBase + i * 16 + l8 + lb3 * 8) * BSKC
                                             + kks * 8 + lb4 * 4) << 2);
                else
                    ad = baseA + (uint32_t)(((kks * 16 + l8 + lb4 * 8) * KTS) << 2)
                               + (uint32_t)((mBase + i * 16 + lb3 * 8) << 1);
                if (AM < 2) ldsm_x4(a[i], ad); else ldsm_x4t(a[i], ad);
            }
#pragma unroll
            for (int j = 0; j < 4; j++) {
                uint32_t bd;
                if (BM < 2)
                    bd = baseB + (uint32_t)(((nBase + j * 8 + lm8) * BSKC
                                             + kks * 8 + lmb3 * 4) << 2);
                else
                    bd = baseB + (uint32_t)(((kks * 16 + lm8 + lmb3 * 8) * KTS) << 2)
                               + (uint32_t)((nBase + j * 8) << 1);
                if (BM < 2) ldsm_x2(b[j], bd); else ldsm_x2t(b[j], bd);
            }
#pragma unroll
            for (int i = 0; i < 4; i++)
#pragma unroll
                for (int j = 0; j < 4; j++)
                    mma_bf16(acc[i][j], a[i], b[j]);
        }
        if (ik + 1 < nk) {
            sts_bf<AM>(sm[cur ^ 1][0], tid, ra);
            sts_bf<BM>(sm[cur ^ 1][1], tid, rb);
        }
        __syncthreads();
    }
}

// ===========================================================================
// cp.async 4-stage pipelined GEMM core, KC variant (k_av)
// ===========================================================================
#define CATILE 20480
#define CA_SMEM (4 * CATILE)

__device__ __forceinline__ void ca_load(uint32_t sdst, const __nv_bfloat16* g,
                                        int ld, int tid) {
    int x = tid >> 2;          // 0..63
    int q = tid & 3;
    const char* gp = (const char*)g;
#pragma unroll
    for (int h = 0; h < 2; h++) {
        int row = x + h * 64;
        asm volatile("cp.async.cg.shared.global [%0], [%1], 16;"
                     :: "r"(sdst + row * 80 + q * 16),
                        "l"(gp + (size_t)row * ld * 2 + q * 16));
    }
}

__device__ __forceinline__ void gemm_ca(const __nv_bfloat16* __restrict__ Ag, int lda,
                                        const __nv_bfloat16* __restrict__ Bg, int ldb,
                                        int K, float acc[4][4][4], uint32_t sbase) {
    const int tid = threadIdx.x;
    const int warp = tid >> 5, lane = tid & 31;
    const int mBase = (warp >> 2) * 64;
    const int nBase = (warp & 3) * 32;
    const int l8 = lane & 7, lb3 = (lane >> 3) & 1, lb4 = (lane >> 4) & 1;
    const int lm = lane & 15, lm8 = lm & 7, lmb3 = (lm >> 3) & 1;

    const int nk = K >> 5;
#pragma unroll
    for (int s = 0; s < 3; s++) {
        if (s < nk) {
            ca_load(sbase + s * CATILE,         Ag + s * 32, lda, tid);
            ca_load(sbase + s * CATILE + 10240, Bg + s * 32, ldb, tid);
        }
        asm volatile("cp.async.commit_group;");
    }
    for (int ik = 0; ik < nk; ik++) {
        asm volatile("cp.async.wait_group 2;");
        __syncthreads();
        const uint32_t baseA = sbase + (ik & 3) * CATILE;
        const uint32_t baseB = baseA + 10240;
#pragma unroll
        for (int kks = 0; kks < 2; kks++) {
            uint32_t a[4][4], b[4][2];
#pragma unroll
            for (int i = 0; i < 4; i++)
                ldsm_x4(a[i], baseA + (uint32_t)(((mBase + i * 16 + l8 + lb3 * 8) * BSKC
                                                  + kks * 8 + lb4 * 4) << 2));
#pragma unroll
            for (int j = 0; j < 4; j++)
                ldsm_x2(b[j], baseB + (uint32_t)(((nBase + j * 8 + lm8) * BSKC
                                                  + kks * 8 + lmb3 * 4) << 2));
#pragma unroll
            for (int i = 0; i < 4; i++)
#pragma unroll
                for (int j = 0; j < 4; j++)
                    mma_bf16(acc[i][j], a[i], b[j]);
        }
        __syncthreads();
        if (ik + 3 < nk) {
            ca_load(sbase + ((ik + 3) & 3) * CATILE,         Ag + (ik + 3) * 32, lda, tid);
            ca_load(sbase + ((ik + 3) & 3) * CATILE + 10240, Bg + (ik + 3) * 32, ldb, tid);
        }
        asm volatile("cp.async.commit_group;");
    }
}

// ===========================================================================
// cp.async 4-stage pipelined GEMM core, KT variant (k_scores)
// ===========================================================================
#define CAKT_TILE 17408
#define CAKT_SMEM (4 * CAKT_TILE)

__device__ __forceinline__ void ca_load_kt(uint32_t sdst, const __nv_bfloat16* g,
                                           int ld, int tid) {
    int row = tid >> 3;        // k-row 0..31
    int seg = tid & 7;         // 16B segment
    const char* gp = (const char*)g + (size_t)row * ld * 2;
    uint32_t sd = sdst + (uint32_t)row * (KTS * 4);
#pragma unroll
    for (int h = 0; h < 2; h++) {
        int sg = seg + h * 8;
        asm volatile("cp.async.cg.shared.global [%0], [%1], 16;"
                     :: "r"(sd + sg * 16), "l"(gp + sg * 16));
    }
}

__device__ __forceinline__ void gemm_ca_kt(const __nv_bfloat16* __restrict__ Ag,
                                           const __nv_bfloat16* __restrict__ Bg,
                                           int ld, int K, float acc[4][4][4],
                                           uint32_t sbase) {
    const int tid = threadIdx.x;
    const int warp = tid >> 5, lane = tid & 31;
    const int mBase = (warp >> 2) * 64;
    const int nBase = (warp & 3) * 32;
    const int l8 = lane & 7, lb3 = (lane >> 3) & 1, lb4 = (lane >> 4) & 1;
    const int lm = lane & 15, lm8 = lm & 7, lmb3 = (lm >> 3) & 1;

    const int nk = K >> 5;
#pragma unroll
    for (int s = 0; s < 3; s++) {
        if (s < nk) {
            ca_load_kt(sbase + s * CAKT_TILE,        Ag + (size_t)s * 32 * ld, ld, tid);
            ca_load_kt(sbase + s * CAKT_TILE + 8704, Bg + (size_t)s * 32 * ld, ld, tid);
        }
        asm volatile("cp.async.commit_group;");
    }
    for (int ik = 0; ik < nk; ik++) {
        asm volatile("cp.async.wait_group 2;");
        __syncthreads();
        const uint32_t baseA = sbase + (ik & 3) * CAKT_TILE;
        const uint32_t baseB = baseA + 8704;
#pragma unroll
        for (int kks = 0; kks < 2; kks++) {
            uint32_t a[4][4], b[4][2];
#pragma unroll
            for (int i = 0; i < 4; i++)
                ldsm_x4t(a[i], baseA + (uint32_t)(((kks * 16 + l8 + lb4 * 8) * KTS) << 2)
                               + (uint32_t)((mBase + i * 16 + lb3 * 8) << 1));
#pragma unroll
            for (int j = 0; j < 4; j++)
                ldsm_x2t(b[j], baseB + (uint32_t)(((kks * 16 + lm8 + lmb3 * 8) * KTS) << 2)
                               + (uint32_t)((nBase + j * 8) << 1));
#pragma unroll
            for (int i = 0; i < 4; i++)
#pragma unroll
                for (int j = 0; j < 4; j++)
                    mma_bf16(acc[i][j], a[i], b[j]);
        }
        __syncthreads();
        if (ik + 3 < nk) {
            ca_load_kt(sbase + ((ik + 3) & 3) * CAKT_TILE,
                       Ag + (size_t)(ik + 3) * 32 * ld, ld, tid);
            ca_load_kt(sbase + ((ik + 3) & 3) * CAKT_TILE + 8704,
                       Bg + (size_t)(ik + 3) * 32 * ld, ld, tid);
        }
        asm volatile("cp.async.commit_group;");
    }
}

// ---------------------------------------------------------------------------
// QKV: q,k,v written [C][T] channel-major (A = pre-converted bf16 weights)
// ---------------------------------------------------------------------------
__global__ void __launch_bounds__(256, 2) k_qkv(const float* __restrict__ bias,
                                                const float* __restrict__ x) {
    int n  = blockIdx.z;
    int m0 = blockIdx.y * 128;
    int t0 = blockIdx.x * 128;
    float acc[4][4][4] = {};
    gemm_bf<0, 3>(g_wq + (size_t)m0 * C, C,
                  x + (size_t)n * C * T + t0, T, C, acc,
                  g_sc + n * C, g_sb + n * C);

    int which = m0 >> 9;
    __nv_bfloat16* dst =
        (which == 0 ? g_q : which == 1 ? g_k : g_v) + (size_t)n * C * T;
    int dbase = m0 & (C - 1);
    const int warp = threadIdx.x >> 5, lane = threadIdx.x & 31;
    const int g = lane >> 2, tg = lane & 3;
    const int mB = (warp >> 2) * 64, nB = (warp & 3) * 32;
#pragma unroll
    for (int i = 0; i < 4; i++) {
        int r = mB + i * 16 + g;
        float bv0 = bias[m0 + r];
        float bv1 = bias[m0 + r + 8];
#pragma unroll
        for (int j = 0; j < 4; j++) {
            int col = t0 + nB + j * 8 + tg * 2;
            uint32_t w0 = packbf(acc[i][j][0] + bv0, acc[i][j][1] + bv0);
            uint32_t w1 = packbf(acc[i][j][2] + bv1, acc[i][j][3] + bv1);
            *(uint32_t*)&dst[(size_t)(dbase + r) * T + col]     = w0;
            *(uint32_t*)&dst[(size_t)(dbase + r + 8) * T + col] = w1;
        }
    }
}

// ---------------------------------------------------------------------------
// scores: p[t][s] = exp(scale * q.k); per-(row, s-tile) sums -> g_lp
// ---------------------------------------------------------------------------
__global__ void __launch_bounds__(256, 2) k_scores() {
    extern __shared__ char smraw[];
    uint32_t sbase = (uint32_t)__cvta_generic_to_shared(smraw);
    int n  = blockIdx.z;
    int t0 = blockIdx.y * 128;
    int s0 = blockIdx.x * 128;
    float acc[4][4][4] = {};
    gemm_ca_kt(g_q + (size_t)n * C * T + t0,
               g_k + (size_t)n * C * T + s0, T, C, acc, sbase);

    const float scale = 0.04419417382415922f;  // 512^-0.5
    __nv_bfloat16* dst = g_p + (size_t)n * T * T;
    __shared__ float sm_l[128][4];
    const int warp = threadIdx.x >> 5, lane = threadIdx.x & 31;
    const int g = lane >> 2, tg = lane & 3;
    const int mB = (warp >> 2) * 64, nB = (warp & 3) * 32;
#pragma unroll
    for (int i = 0; i < 4; i++) {
        int r = t0 + mB + i * 16 + g;
        float ps0 = 0.f, ps1 = 0.f;
#pragma unroll
        for (int j = 0; j < 4; j++) {
            int col = s0 + nB + j * 8 + tg * 2;
            float e0 = __expf(acc[i][j][0] * scale);
            float e1 = __expf(acc[i][j][1] * scale);
            float e2 = __expf(acc[i][j][2] * scale);
            float e3 = __expf(acc[i][j][3] * scale);
            ps0 += e0 + e1;
            ps1 += e2 + e3;
            *(uint32_t*)&dst[(size_t)r * T + col]       = packbf(e0, e1);
            *(uint32_t*)&dst[(size_t)(r + 8) * T + col] = packbf(e2, e3);
        }
        ps0 += __shfl_xor_sync(0xffffffffu, ps0, 1);
        ps0 += __shfl_xor_sync(0xffffffffu, ps0, 2);
        ps1 += __shfl_xor_sync(0xffffffffu, ps1, 1);
        ps1 += __shfl_xor_sync(0xffffffffu, ps1, 2);
        if (tg == 0) {
            sm_l[mB + i * 16 + g][warp & 3]     = ps0;
            sm_l[mB + i * 16 + g + 8][warp & 3] = ps1;
        }
    }
    __syncthreads();
    if (threadIdx.x < 128) {
        float l = sm_l[threadIdx.x][0] + sm_l[threadIdx.x][1]
                + sm_l[threadIdx.x][2] + sm_l[threadIdx.x][3];
        g_lp[((size_t)n * 32 + blockIdx.x) * T + t0 + threadIdx.x] = l;
    }
}

// ---------------------------------------------------------------------------
// inv row sum (fixed order, deterministic)
// ---------------------------------------------------------------------------
__global__ void __launch_bounds__(256) k_lsum() {
    int idx = blockIdx.x * 256 + threadIdx.x;
    int n = idx >> 12, t = idx & (T - 1);
    const float* lp = g_lp + (size_t)n * 32 * T + t;
    float l = 0.f;
#pragma unroll
    for (int i = 0; i < 32; i++) l += lp[(size_t)i * T];
    g_li[idx] = 1.f / l;
}

// ---------------------------------------------------------------------------
// AV: o[t][c] = inv_l[t] * sum_s p[t][s] * v[c][s]
// ---------------------------------------------------------------------------
__global__ void __launch_bounds__(256, 2) k_av() {
    extern __shared__ char smraw[];
    uint32_t sbase = (uint32_t)__cvta_generic_to_shared(smraw);
    int n  = blockIdx.z;
    int t0 = blockIdx.y * 128;
    int c0 = blockIdx.x * 128;
    float acc[4][4][4] = {};
    gemm_ca(g_p + ((size_t)n * T + t0) * T, T,
            g_v + ((size_t)n * C + c0) * T, T, T, acc, sbase);

    __nv_bfloat16* dst = g_o + (size_t)n * T * C;
    const int warp = threadIdx.x >> 5, lane = threadIdx.x & 31;
    const int g = lane >> 2, tg = lane & 3;
    const int mB = (warp >> 2) * 64, nB = (warp & 3) * 32;
#pragma unroll
    for (int i = 0; i < 4; i++) {
        int r = t0 + mB + i * 16 + g;
        float inv0 = g_li[n * T + r];
        float inv1 = g_li[n * T + r + 8];
#pragma unroll
        for (int j = 0; j < 4; j++) {
            int col = c0 + nB + j * 8 + tg * 2;
            uint32_t w0 = packbf(acc[i][j][0] * inv0, acc[i][j][1] * inv0);
            uint32_t w1 = packbf(acc[i][j][2] * inv1, acc[i][j][3] * inv1);
            *(uint32_t*)&dst[(size_t)r * C + col]       = w0;
            *(uint32_t*)&dst[(size_t)(r + 8) * C + col] = w1;
        }
    }
}

// ---------------------------------------------------------------------------
// proj: out[n][d][t] = proj_w[d][:] . o[t][:] + proj_b[d] + x[n][d][t]
// ---------------------------------------------------------------------------
__global__ void __launch_bounds__(256, 2) k_proj(const float* __restrict__ bias,
                                                 const float* __restrict__ x,
                                                 float* __restrict__ out) {
    int n  = blockIdx.z;
    int d0 = blockIdx.y * 128;
    int t0 = blockIdx.x * 128;
    float acc[4][4][4] = {};
    gemm_bf<0, 0>(g_wp + (size_t)d0 * C, C,
                  g_o + (size_t)n * T * C + (size_t)t0 * C, C, C, acc);

    const int warp = threadIdx.x >> 5, lane = threadIdx.x & 31;
    const int g = lane >> 2, tg = lane & 3;
    const int mB = (warp >> 2) * 64, nB = (warp & 3) * 32;
#pragma unroll
    for (int i = 0; i < 4; i++) {
        int d = d0 + mB + i * 16 + g;
        float bv0 = bias[d];
        float bv1 = bias[d + 8];
#pragma unroll
        for (int j = 0; j < 4; j++) {
            int col = t0 + nB + j * 8 + tg * 2;
            size_t base0 = ((size_t)n * C + d) * T + col;
            size_t base1 = ((size_t)n * C + d + 8) * T + col;
            float2 x0 = *(const float2*)&x[base0];
            float2 x1 = *(const float2*)&x[base1];
            float2 v0 = { acc[i][j][0] + bv0 + x0.x, acc[i][j][1] + bv0 + x0.y };
            float2 v1 = { acc[i][j][2] + bv1 + x1.x, acc[i][j][3] + bv1 + x1.y };
            *(float2*)&out[base0] = v0;
            *(float2*)&out[base1] = v1;
        }
    }
}

// ---------------------------------------------------------------------------
extern "C" void kernel_launch(void* const* d_in, const int* in_sizes, int n_in,
                              void* d_out, int out_size) {
    const float* x      = (const float*)d_in[0];
    const float* gn_w   = (const float*)d_in[1];
    const float* gn_b   = (const float*)d_in[2];
    const float* qkv_w  = (const float*)d_in[3];
    const float* qkv_b  = (const float*)d_in[4];
    const float* proj_w = (const float*)d_in[5];
    const float* proj_b = (const float*)d_in[6];
    float* out = (float*)d_out;

    cudaFuncSetAttribute(k_av,     cudaFuncAttributeMaxDynamicSharedMemorySize, CA_SMEM);
    cudaFuncSetAttribute(k_scores, cudaFuncAttributeMaxDynamicSharedMemorySize, CAKT_SMEM);

    k_cvt   <<<(NQ4 + NP4) / 256, 256>>>(qkv_w, proj_w);
    gn_stats<<<NB * GROUPS, 256>>>(x, gn_w, gn_b);
    k_qkv   <<<dim3(T / 128, (3 * C) / 128, NB), 256>>>(qkv_b, x);
    k_scores<<<dim3(T / 128, T / 128, NB), 256, CAKT_SMEM>>>();
    k_lsum  <<<NB * T / 256, 256>>>();
    k_av    <<<dim3(C / 128, T / 128, NB), 256, CA_SMEM>>>();
    k_proj  <<<dim3(T / 128, C / 128, NB), 256>>>(proj_b, x, out);
}

// round 17
// speedup vs baseline: 1.0699x; 1.0141x over previous
#include <cuda_runtime.h>
#include <cuda_bf16.h>
#include <cstdint>

#define NB 8
#define C 512
#define T 4096
#define GROUPS 32
#define CPG (C / GROUPS)      // 16
#define GSZ (CPG * T)         // 65536 elements per group

// Scratch (device globals; no allocations allowed)
__device__ float g_sc[NB * C];                         // GN scale  per (n,c)
__device__ float g_sb[NB * C];                         // GN shift  per (n,c)
__device__ __nv_bfloat16 g_wq[3 * C * C];              // qkv_w bf16
__device__ __nv_bfloat16 g_wp[C * C];                  // proj_w bf16
__device__ __nv_bfloat16 g_q[(size_t)NB * C * T];      // [N][C][T]
__device__ __nv_bfloat16 g_k[(size_t)NB * C * T];      // [N][C][T]
__device__ __nv_bfloat16 g_v[(size_t)NB * C * T];      // [N][C][T]
__device__ __nv_bfloat16 g_o[(size_t)NB * T * C];      // [N][T][C]
__device__ __nv_bfloat16 g_p[(size_t)NB * T * T];      // [N][T][T] bf16 exp(S)
__device__ float g_lp[(size_t)NB * 32 * T];            // partial row sums
__device__ float g_li[NB * T];                         // 1 / row sum

__device__ __forceinline__ uint32_t packbf(float lo, float hi) {
    __nv_bfloat162 h = __float22bfloat162_rn(make_float2(lo, hi));
    return *(uint32_t*)&h;
}

// ---------------------------------------------------------------------------
// Weight pre-conversion: fp32 -> bf16 once per launch
// ---------------------------------------------------------------------------
#define NQ4 (3 * C * C / 4)   // 196608 float4s in qkv_w
#define NP4 (C * C / 4)       // 65536  float4s in proj_w
__global__ void __launch_bounds__(256) k_cvt(const float* __restrict__ qw,
                                             const float* __restrict__ pw) {
    int idx = blockIdx.x * 256 + threadIdx.x;
    float4 v;
    uint2* dst;
    if (idx < NQ4) {
        v = ((const float4*)qw)[idx];
        dst = (uint2*)g_wq + idx;
    } else {
        v = ((const float4*)pw)[idx - NQ4];
        dst = (uint2*)g_wp + (idx - NQ4);
    }
    *dst = make_uint2(packbf(v.x, v.y), packbf(v.z, v.w));
}

// ---------------------------------------------------------------------------
// GroupNorm stats: one block per (n, group); writes per-channel scale/shift
// ---------------------------------------------------------------------------
__global__ void __launch_bounds__(256) gn_stats(const float* __restrict__ x,
                                                const float* __restrict__ w,
                                                const float* __restrict__ b) {
    int n = blockIdx.x >> 5;
    int g = blockIdx.x & 31;
    const float4* xp = (const float4*)(x + ((size_t)n * C + g * CPG) * T);
    const int NV = GSZ / 4;

    float s = 0.f, s2 = 0.f;
    for (int i = threadIdx.x; i < NV; i += 256) {
        float4 v = xp[i];
        s  += v.x + v.y + v.z + v.w;
        s2 += v.x * v.x + v.y * v.y + v.z * v.z + v.w * v.w;
    }
    __shared__ float rs[32], rs2[32];
    int lid = threadIdx.x & 31, wid = threadIdx.x >> 5;
#pragma unroll
    for (int o = 16; o; o >>= 1) {
        s  += __shfl_xor_sync(0xffffffffu, s, o);
        s2 += __shfl_xor_sync(0xffffffffu, s2, o);
    }
    if (lid == 0) { rs[wid] = s; rs2[wid] = s2; }
    __syncthreads();
    if (wid == 0) {
        s  = (lid < 8) ? rs[lid]  : 0.f;
        s2 = (lid < 8) ? rs2[lid] : 0.f;
#pragma unroll
        for (int o = 4; o; o >>= 1) {
            s  += __shfl_xor_sync(0xffffffffu, s, o);
            s2 += __shfl_xor_sync(0xffffffffu, s2, o);
        }
        if (lid == 0) { rs[0] = s; rs2[0] = s2; }
    }
    __syncthreads();
    float mean = rs[0] * (1.f / GSZ);
    float var  = rs2[0] * (1.f / GSZ) - mean * mean;
    float inv  = rsqrtf(var + 1e-5f);

    if (threadIdx.x < CPG) {
        int c = g * CPG + threadIdx.x;
        float scv = w[c] * inv;
        g_sc[n * C + c] = scv;
        g_sb[n * C + c] = b[c] - mean * scv;
    }
}

// ===========================================================================
// Common helpers
// ===========================================================================
#define BSKC 20
#define KTS  68
#define BSMW 2560

__device__ __forceinline__ void ldsm_x4(uint32_t a[4], uint32_t addr) {
    asm volatile("ldmatrix.sync.aligned.m8n8.x4.shared.b16 {%0,%1,%2,%3}, [%4];"
                 : "=r"(a[0]), "=r"(a[1]), "=r"(a[2]), "=r"(a[3]) : "r"(addr));
}
__device__ __forceinline__ void ldsm_x4t(uint32_t a[4], uint32_t addr) {
    asm volatile("ldmatrix.sync.aligned.m8n8.x4.trans.shared.b16 {%0,%1,%2,%3}, [%4];"
                 : "=r"(a[0]), "=r"(a[1]), "=r"(a[2]), "=r"(a[3]) : "r"(addr));
}
__device__ __forceinline__ void ldsm_x2(uint32_t b[2], uint32_t addr) {
    asm volatile("ldmatrix.sync.aligned.m8n8.x2.shared.b16 {%0,%1}, [%2];"
                 : "=r"(b[0]), "=r"(b[1]) : "r"(addr));
}
__device__ __forceinline__ void ldsm_x2t(uint32_t b[2], uint32_t addr) {
    asm volatile("ldmatrix.sync.aligned.m8n8.x2.trans.shared.b16 {%0,%1}, [%2];"
                 : "=r"(b[0]), "=r"(b[1]) : "r"(addr));
}
__device__ __forceinline__ void mma_bf16(float acc[4], const uint32_t a[4],
                                         const uint32_t b[2]) {
    asm("mma.sync.aligned.m16n8k16.row.col.f32.bf16.bf16.f32 "
        "{%0,%1,%2,%3},{%4,%5,%6,%7},{%8,%9},{%0,%1,%2,%3};"
        : "+f"(acc[0]), "+f"(acc[1]), "+f"(acc[2]), "+f"(acc[3])
        : "r"(a[0]), "r"(a[1]), "r"(a[2]), "r"(a[3]), "r"(b[0]), "r"(b[1]));
}

// ===========================================================================
// mma.sync bf16 GEMM core, register double-buffer (qkv & proj)
//   MODE 0: KC bf16; MODE 1: KC fp32; MODE 2: KT bf16; MODE 3: KT fp32 + GN
// ===========================================================================
template <int MODE>
__device__ __forceinline__ void ldg_bf(const void* gp, int ld, int k0, int tid,
                                       uint4 r[2],
                                       const float* __restrict__ sc,
                                       const float* __restrict__ sb) {
    if (MODE == 0) {
        const __nv_bfloat16* g = (const __nv_bfloat16*)gp;
        int x = tid >> 1, kq = (tid & 1) << 4;
        const uint4* p = (const uint4*)(g + (size_t)x * ld + k0 + kq);
        r[0] = p[0];
        r[1] = p[1];
    } else if (MODE == 1) {
        const float* g = (const float*)gp;
        int x = tid >> 1, kq = (tid & 1) << 4;
        const float4* p = (const float4*)(g + (size_t)x * ld + k0 + kq);
        float4 f0 = p[0], f1 = p[1], f2 = p[2], f3 = p[3];
        r[0].x = packbf(f0.x, f0.y); r[0].y = packbf(f0.z, f0.w);
        r[0].z = packbf(f1.x, f1.y); r[0].w = packbf(f1.z, f1.w);
        r[1].x = packbf(f2.x, f2.y); r[1].y = packbf(f2.z, f2.w);
        r[1].z = packbf(f3.x, f3.y); r[1].w = packbf(f3.z, f3.w);
    } else if (MODE == 2) {
        const __nv_bfloat16* g = (const __nv_bfloat16*)gp;
        int kw = tid >> 5, x4 = (tid & 31) << 2;
        const __nv_bfloat16* base = g + (size_t)(k0 + 2 * kw) * ld + x4;
        uint2 u0 = *(const uint2*)base;
        uint2 u1 = *(const uint2*)(base + ld);
        uint2 u2 = *(const uint2*)(base + (size_t)16 * ld);
        uint2 u3 = *(const uint2*)(base + (size_t)17 * ld);
        r[0].x = u0.x; r[0].y = u0.y; r[0].z = u1.x; r[0].w = u1.y;
        r[1].x = u2.x; r[1].y = u2.y; r[1].z = u3.x; r[1].w = u3.y;
    } else {
        const float* g = (const float*)gp;
        int kw = tid >> 5, x4 = (tid & 31) << 2;
        int kr = k0 + 2 * kw;
        const float* base = g + (size_t)kr * ld + x4;
        float4 f0 = *(const float4*)base;
        float4 f1 = *(const float4*)(base + ld);
        float4 f2 = *(const float4*)(base + (size_t)16 * ld);
        float4 f3 = *(const float4*)(base + (size_t)17 * ld);
        float s0 = sc[kr],      o0 = sb[kr];
        float s1 = sc[kr + 1],  o1 = sb[kr + 1];
        float s2 = sc[kr + 16], o2 = sb[kr + 16];
        float s3 = sc[kr + 17], o3 = sb[kr + 17];
        r[0].x = packbf(f0.x * s0 + o0, f0.y * s0 + o0);
        r[0].y = packbf(f0.z * s0 + o0, f0.w * s0 + o0);
        r[0].z = packbf(f1.x * s1 + o1, f1.y * s1 + o1);
        r[0].w = packbf(f1.z * s1 + o1, f1.w * s1 + o1);
        r[1].x = packbf(f2.x * s2 + o2, f2.y * s2 + o2);
        r[1].y = packbf(f2.z * s2 + o2, f2.w * s2 + o2);
        r[1].z = packbf(f3.x * s3 + o3, f3.y * s3 + o3);
        r[1].w = packbf(f3.z * s3 + o3, f3.w * s3 + o3);
    }
}

template <int MODE>
__device__ __forceinline__ void sts_bf(uint32_t* s, int tid, const uint4 r[2]) {
    if (MODE >= 2) {
        int kw = tid >> 5, xw = (tid & 31) * 2;
        *(uint2*)(s + (2 * kw) * KTS + xw)      = make_uint2(r[0].x, r[0].y);
        *(uint2*)(s + (2 * kw + 1) * KTS + xw)  = make_uint2(r[0].z, r[0].w);
        *(uint2*)(s + (2 * kw + 16) * KTS + xw) = make_uint2(r[1].x, r[1].y);
        *(uint2*)(s + (2 * kw + 17) * KTS + xw) = make_uint2(r[1].z, r[1].w);
    } else {
        int x = tid >> 1, kq8 = (tid & 1) << 3;
        *(uint4*)(s + x * BSKC + kq8)     = r[0];
        *(uint4*)(s + x * BSKC + kq8 + 4) = r[1];
    }
}

template <int AM, int BM>
__device__ __forceinline__ void gemm_bf(const void* Ag, int lda,
                                        const void* Bg, int ldb,
                                        int K, float acc[4][4][4],
                                        const float* bsc = nullptr,
                                        const float* bsb = nullptr) {
    __shared__ uint32_t sm[2][2][BSMW];
    const int tid = threadIdx.x;
    const int warp = tid >> 5, lane = tid & 31;
    const int mBase = (warp >> 2) * 64;
    const int nBase = (warp & 3) * 32;
    const int l8 = lane & 7, lb3 = (lane >> 3) & 1, lb4 = (lane >> 4) & 1;
    const int lm = lane & 15, lm8 = lm & 7, lmb3 = (lm >> 3) & 1;

    const uint32_t smAddr = (uint32_t)__cvta_generic_to_shared(&sm[0][0][0]);

    uint4 ra[2], rb[2];
    ldg_bf<AM>(Ag, lda, 0, tid, ra, nullptr, nullptr);
    ldg_bf<BM>(Bg, ldb, 0, tid, rb, bsc, bsb);
    sts_bf<AM>(sm[0][0], tid, ra);
    sts_bf<BM>(sm[0][1], tid, rb);
    __syncthreads();

    const int nk = K >> 5;
    for (int ik = 0; ik < nk; ik++) {
        const int cur = ik & 1;
        if (ik + 1 < nk) {
            ldg_bf<AM>(Ag, lda, (ik + 1) << 5, tid, ra, nullptr, nullptr);
            ldg_bf<BM>(Bg, ldb, (ik + 1) << 5, tid, rb, bsc, bsb);
        }
        const uint32_t baseA = smAddr + (uint32_t)(cur * 2 + 0) * (BSMW * 4);
        const uint32_t baseB = smAddr + (uint32_t)(cur * 2 + 1) * (BSMW * 4);
#pragma unroll
        for (int kks = 0; kks < 2; kks++) {
            uint32_t a[4][4], b[4][2];
#pragma unroll
            for (int i = 0; i < 4; i++) {
                uint32_t ad;
                if (AM < 2)
                    ad = baseA + (uint32_t)(((mBase + i * 16 + l8 + lb3 * 8) * BSKC
                                             + kks * 8 + lb4 * 4) << 2);
                else
                    ad = baseA + (uint32_t)(((kks * 16 + l8 + lb4 * 8) * KTS) << 2)
                               + (uint32_t)((mBase + i * 16 + lb3 * 8) << 1);
                if (AM < 2) ldsm_x4(a[i], ad); else ldsm_x4t(a[i], ad);
            }
#pragma unroll
            for (int j = 0; j < 4; j++) {
                uint32_t bd;
                if (BM < 2)
                    bd = baseB + (uint32_t)(((nBase + j * 8 + lm8) * BSKC
                                             + kks * 8 + lmb3 * 4) << 2);
                else
                    bd = baseB + (uint32_t)(((kks * 16 + lm8 + lmb3 * 8) * KTS) << 2)
                               + (uint32_t)((nBase + j * 8) << 1);
                if (BM < 2) ldsm_x2(b[j], bd); else ldsm_x2t(b[j], bd);
            }
#pragma unroll
            for (int i = 0; i < 4; i++)
#pragma unroll
                for (int j = 0; j < 4; j++)
                    mma_bf16(acc[i][j], a[i], b[j]);
        }
        if (ik + 1 < nk) {
            sts_bf<AM>(sm[cur ^ 1][0], tid, ra);
            sts_bf<BM>(sm[cur ^ 1][1], tid, rb);
        }
        __syncthreads();
    }
}

// ===========================================================================
// cp.async 4-stage pipelined GEMM core, KC variant (k_av)
// ===========================================================================
#define CATILE 20480
#define CA_SMEM (4 * CATILE)

__device__ __forceinline__ void ca_load(uint32_t sdst, const __nv_bfloat16* g,
                                        int ld, int tid) {
    int x = tid >> 2;          // 0..63
    int q = tid & 3;
    const char* gp = (const char*)g;
#pragma unroll
    for (int h = 0; h < 2; h++) {
        int row = x + h * 64;
        asm volatile("cp.async.cg.shared.global [%0], [%1], 16;"
                     :: "r"(sdst + row * 80 + q * 16),
                        "l"(gp + (size_t)row * ld * 2 + q * 16));
    }
}

__device__ __forceinline__ void gemm_ca(const __nv_bfloat16* __restrict__ Ag, int lda,
                                        const __nv_bfloat16* __restrict__ Bg, int ldb,
                                        int K, float acc[4][4][4], uint32_t sbase) {
    const int tid = threadIdx.x;
    const int warp = tid >> 5, lane = tid & 31;
    const int mBase = (warp >> 2) * 64;
    const int nBase = (warp & 3) * 32;
    const int l8 = lane & 7, lb3 = (lane >> 3) & 1, lb4 = (lane >> 4) & 1;
    const int lm = lane & 15, lm8 = lm & 7, lmb3 = (lm >> 3) & 1;

    const int nk = K >> 5;
#pragma unroll
    for (int s = 0; s < 3; s++) {
        if (s < nk) {
            ca_load(sbase + s * CATILE,         Ag + s * 32, lda, tid);
            ca_load(sbase + s * CATILE + 10240, Bg + s * 32, ldb, tid);
        }
        asm volatile("cp.async.commit_group;");
    }
    for (int ik = 0; ik < nk; ik++) {
        asm volatile("cp.async.wait_group 2;");
        __syncthreads();
        const uint32_t baseA = sbase + (ik & 3) * CATILE;
        const uint32_t baseB = baseA + 10240;
#pragma unroll
        for (int kks = 0; kks < 2; kks++) {
            uint32_t a[4][4], b[4][2];
#pragma unroll
            for (int i = 0; i < 4; i++)
                ldsm_x4(a[i], baseA + (uint32_t)(((mBase + i * 16 + l8 + lb3 * 8) * BSKC
                                                  + kks * 8 + lb4 * 4) << 2));
#pragma unroll
            for (int j = 0; j < 4; j++)
                ldsm_x2(b[j], baseB + (uint32_t)(((nBase + j * 8 + lm8) * BSKC
                                                  + kks * 8 + lmb3 * 4) << 2));
#pragma unroll
            for (int i = 0; i < 4; i++)
#pragma unroll
                for (int j = 0; j < 4; j++)
                    mma_bf16(acc[i][j], a[i], b[j]);
        }
        __syncthreads();
        if (ik + 3 < nk) {
            ca_load(sbase + ((ik + 3) & 3) * CATILE,         Ag + (ik + 3) * 32, lda, tid);
            ca_load(sbase + ((ik + 3) & 3) * CATILE + 10240, Bg + (ik + 3) * 32, ldb, tid);
        }
        asm volatile("cp.async.commit_group;");
    }
}

// ===========================================================================
// cp.async 3-stage pipelined GEMM core, KT variant with K-chunk = 64
// (k_scores). Stage: 64 k-rows x 272 B per operand = 17408 B; A+B = 34816 B.
// ===========================================================================
#define CAKT_TILE 34816
#define CAKT_SMEM (3 * CAKT_TILE)

__device__ __forceinline__ void ca_load_kt(uint32_t sdst, const __nv_bfloat16* g,
                                           int ld, int tid) {
    int row = tid >> 3;        // k-row 0..31
    int seg = tid & 7;         // 16B segment
#pragma unroll
    for (int rr = 0; rr < 2; rr++) {
        int r = row + rr * 32;
        const char* gp = (const char*)g + (size_t)r * ld * 2;
        uint32_t sd = sdst + (uint32_t)r * (KTS * 4);
#pragma unroll
        for (int h = 0; h < 2; h++) {
            int sg = seg + h * 8;
            asm volatile("cp.async.cg.shared.global [%0], [%1], 16;"
                         :: "r"(sd + sg * 16), "l"(gp + sg * 16));
        }
    }
}

__device__ __forceinline__ void gemm_ca_kt(const __nv_bfloat16* __restrict__ Ag,
                                           const __nv_bfloat16* __restrict__ Bg,
                                           int ld, int K, float acc[4][4][4],
                                           uint32_t sbase) {
    const int tid = threadIdx.x;
    const int warp = tid >> 5, lane = tid & 31;
    const int mBase = (warp >> 2) * 64;
    const int nBase = (warp & 3) * 32;
    const int l8 = lane & 7, lb3 = (lane >> 3) & 1, lb4 = (lane >> 4) & 1;
    const int lm = lane & 15, lm8 = lm & 7, lmb3 = (lm >> 3) & 1;

    const int nk = K >> 6;    // chunks of 64
#pragma unroll
    for (int s = 0; s < 2; s++) {
        if (s < nk) {
            ca_load_kt(sbase + s * CAKT_TILE,         Ag + (size_t)s * 64 * ld, ld, tid);
            ca_load_kt(sbase + s * CAKT_TILE + 17408, Bg + (size_t)s * 64 * ld, ld, tid);
        }
        asm volatile("cp.async.commit_group;");
    }
    for (int ik = 0; ik < nk; ik++) {
        asm volatile("cp.async.wait_group 1;");
        __syncthreads();
        int slot = ik % 3;
        const uint32_t baseA = sbase + slot * CAKT_TILE;
        const uint32_t baseB = baseA + 17408;
#pragma unroll
        for (int kks = 0; kks < 4; kks++) {
            uint32_t a[4][4], b[4][2];
#pragma unroll
            for (int i = 0; i < 4; i++)
                ldsm_x4t(a[i], baseA + (uint32_t)(((kks * 16 + l8 + lb4 * 8) * KTS) << 2)
                               + (uint32_t)((mBase + i * 16 + lb3 * 8) << 1));
#pragma unroll
            for (int j = 0; j < 4; j++)
                ldsm_x2t(b[j], baseB + (uint32_t)(((kks * 16 + lm8 + lmb3 * 8) * KTS) << 2)
                               + (uint32_t)((nBase + j * 8) << 1));
#pragma unroll
            for (int i = 0; i < 4; i++)
#pragma unroll
                for (int j = 0; j < 4; j++)
                    mma_bf16(acc[i][j], a[i], b[j]);
        }
        if (ik + 2 < nk) {
            int ns = (ik + 2) % 3;
            ca_load_kt(sbase + ns * CAKT_TILE,
                       Ag + (size_t)(ik + 2) * 64 * ld, ld, tid);
            ca_load_kt(sbase + ns * CAKT_TILE + 17408,
                       Bg + (size_t)(ik + 2) * 64 * ld, ld, tid);
        }
        asm volatile("cp.async.commit_group;");
    }
}

// ---------------------------------------------------------------------------
// QKV: q,k,v written [C][T] channel-major (A = pre-converted bf16 weights)
// ---------------------------------------------------------------------------
__global__ void __launch_bounds__(256, 2) k_qkv(const float* __restrict__ bias,
                                                const float* __restrict__ x) {
    int n  = blockIdx.z;
    int m0 = blockIdx.y * 128;
    int t0 = blockIdx.x * 128;
    float acc[4][4][4] = {};
    gemm_bf<0, 3>(g_wq + (size_t)m0 * C, C,
                  x + (size_t)n * C * T + t0, T, C, acc,
                  g_sc + n * C, g_sb + n * C);

    int which = m0 >> 9;
    __nv_bfloat16* dst =
        (which == 0 ? g_q : which == 1 ? g_k : g_v) + (size_t)n * C * T;
    int dbase = m0 & (C - 1);
    const int warp = threadIdx.x >> 5, lane = threadIdx.x & 31;
    const int g = lane >> 2, tg = lane & 3;
    const int mB = (warp >> 2) * 64, nB = (warp & 3) * 32;
#pragma unroll
    for (int i = 0; i < 4; i++) {
        int r = mB + i * 16 + g;
        float bv0 = bias[m0 + r];
        float bv1 = bias[m0 + r + 8];
#pragma unroll
        for (int j = 0; j < 4; j++) {
            int col = t0 + nB + j * 8 + tg * 2;
            uint32_t w0 = packbf(acc[i][j][0] + bv0, acc[i][j][1] + bv0);
            uint32_t w1 = packbf(acc[i][j][2] + bv1, acc[i][j][3] + bv1);
            *(uint32_t*)&dst[(size_t)(dbase + r) * T + col]     = w0;
            *(uint32_t*)&dst[(size_t)(dbase + r + 8) * T + col] = w1;
        }
    }
}

// ---------------------------------------------------------------------------
// scores: p[t][s] = exp(scale * q.k); per-(row, s-tile) sums -> g_lp
// ---------------------------------------------------------------------------
__global__ void __launch_bounds__(256, 2) k_scores() {
    extern __shared__ char smraw[];
    uint32_t sbase = (uint32_t)__cvta_generic_to_shared(smraw);
    int n  = blockIdx.z;
    int t0 = blockIdx.y * 128;
    int s0 = blockIdx.x * 128;
    float acc[4][4][4] = {};
    gemm_ca_kt(g_q + (size_t)n * C * T + t0,
               g_k + (size_t)n * C * T + s0, T, C, acc, sbase);

    const float scale = 0.04419417382415922f;  // 512^-0.5
    __nv_bfloat16* dst = g_p + (size_t)n * T * T;
    __shared__ float sm_l[128][4];
    const int warp = threadIdx.x >> 5, lane = threadIdx.x & 31;
    const int g = lane >> 2, tg = lane & 3;
    const int mB = (warp >> 2) * 64, nB = (warp & 3) * 32;
#pragma unroll
    for (int i = 0; i < 4; i++) {
        int r = t0 + mB + i * 16 + g;
        float ps0 = 0.f, ps1 = 0.f;
#pragma unroll
        for (int j = 0; j < 4; j++) {
            int col = s0 + nB + j * 8 + tg * 2;
            float e0 = __expf(acc[i][j][0] * scale);
            float e1 = __expf(acc[i][j][1] * scale);
            float e2 = __expf(acc[i][j][2] * scale);
            float e3 = __expf(acc[i][j][3] * scale);
            ps0 += e0 + e1;
            ps1 += e2 + e3;
            *(uint32_t*)&dst[(size_t)r * T + col]       = packbf(e0, e1);
            *(uint32_t*)&dst[(size_t)(r + 8) * T + col] = packbf(e2, e3);
        }
        ps0 += __shfl_xor_sync(0xffffffffu, ps0, 1);
        ps0 += __shfl_xor_sync(0xffffffffu, ps0, 2);
        ps1 += __shfl_xor_sync(0xffffffffu, ps1, 1);
        ps1 += __shfl_xor_sync(0xffffffffu, ps1, 2);
        if (tg == 0) {
            sm_l[mB + i * 16 + g][warp & 3]     = ps0;
            sm_l[mB + i * 16 + g + 8][warp & 3] = ps1;
        }
    }
    __syncthreads();
    if (threadIdx.x < 128) {
        float l = sm_l[threadIdx.x][0] + sm_l[threadIdx.x][1]
                + sm_l[threadIdx.x][2] + sm_l[threadIdx.x][3];
        g_lp[((size_t)n * 32 + blockIdx.x) * T + t0 + threadIdx.x] = l;
    }
}

// ---------------------------------------------------------------------------
// inv row sum (fixed order, deterministic)
// ---------------------------------------------------------------------------
__global__ void __launch_bounds__(256) k_lsum() {
    int idx = blockIdx.x * 256 + threadIdx.x;
    int n = idx >> 12, t = idx & (T - 1);
    const float* lp = g_lp + (size_t)n * 32 * T + t;
    float l = 0.f;
#pragma unroll
    for (int i = 0; i < 32; i++) l += lp[(size_t)i * T];
    g_li[idx] = 1.f / l;
}

// ---------------------------------------------------------------------------
// AV: o[t][c] = inv_l[t] * sum_s p[t][s] * v[c][s]
// ---------------------------------------------------------------------------
__global__ void __launch_bounds__(256, 2) k_av() {
    extern __shared__ char smraw[];
    uint32_t sbase = (uint32_t)__cvta_generic_to_shared(smraw);
    int n  = blockIdx.z;
    int t0 = blockIdx.y * 128;
    int c0 = blockIdx.x * 128;
    float acc[4][4][4] = {};
    gemm_ca(g_p + ((size_t)n * T + t0) * T, T,
            g_v + ((size_t)n * C + c0) * T, T, T, acc, sbase);

    __nv_bfloat16* dst = g_o + (size_t)n * T * C;
    const int warp = threadIdx.x >> 5, lane = threadIdx.x & 31;
    const int g = lane >> 2, tg = lane & 3;
    const int mB = (warp >> 2) * 64, nB = (warp & 3) * 32;
#pragma unroll
    for (int i = 0; i < 4; i++) {
        int r = t0 + mB + i * 16 + g;
        float inv0 = g_li[n * T + r];
        float inv1 = g_li[n * T + r + 8];
#pragma unroll
        for (int j = 0; j < 4; j++) {
            int col = c0 + nB + j * 8 + tg * 2;
            uint32_t w0 = packbf(acc[i][j][0] * inv0, acc[i][j][1] * inv0);
            uint32_t w1 = packbf(acc[i][j][2] * inv1, acc[i][j][3] * inv1);
            *(uint32_t*)&dst[(size_t)r * C + col]       = w0;
            *(uint32_t*)&dst[(size_t)(r + 8) * C + col] = w1;
        }
    }
}

// ---------------------------------------------------------------------------
// proj: out[n][d][t] = proj_w[d][:] . o[t][:] + proj_b[d] + x[n][d][t]
// ---------------------------------------------------------------------------
__global__ void __launch_bounds__(256, 2) k_proj(const float* __restrict__ bias,
                                                 const float* __restrict__ x,
                                                 float* __restrict__ out) {
    int n  = blockIdx.z;
    int d0 = blockIdx.y * 128;
    int t0 = blockIdx.x * 128;
    float acc[4][4][4] = {};
    gemm_bf<0, 0>(g_wp + (size_t)d0 * C, C,
                  g_o + (size_t)n * T * C + (size_t)t0 * C, C, C, acc);

    const int warp = threadIdx.x >> 5, lane = threadIdx.x & 31;
    const int g = lane >> 2, tg = lane & 3;
    const int mB = (warp >> 2) * 64, nB = (warp & 3) * 32;
#pragma unroll
    for (int i = 0; i < 4; i++) {
        int d = d0 + mB + i * 16 + g;
        float bv0 = bias[d];
        float bv1 = bias[d + 8];
#pragma unroll
        for (int j = 0; j < 4; j++) {
            int col = t0 + nB + j * 8 + tg * 2;
            size_t base0 = ((size_t)n * C + d) * T + col;
            size_t base1 = ((size_t)n * C + d + 8) * T + col;
            float2 x0 = *(const float2*)&x[base0];
            float2 x1 = *(const float2*)&x[base1];
            float2 v0 = { acc[i][j][0] + bv0 + x0.x, acc[i][j][1] + bv0 + x0.y };
            float2 v1 = { acc[i][j][2] + bv1 + x1.x, acc[i][j][3] + bv1 + x1.y };
            *(float2*)&out[base0] = v0;
            *(float2*)&out[base1] = v1;
        }
    }
}

// ---------------------------------------------------------------------------
extern "C" void kernel_launch(void* const* d_in, const int* in_sizes, int n_in,
                              void* d_out, int out_size) {
    const float* x      = (const float*)d_in[0];
    const float* gn_w   = (const float*)d_in[1];
    const float* gn_b   = (const float*)d_in[2];
    const float* qkv_w  = (const float*)d_in[3];
    const float* qkv_b  = (const float*)d_in[4];
    const float* proj_w = (const float*)d_in[5];
    const float* proj_b = (const float*)d_in[6];
    float* out = (float*)d_out;

    cudaFuncSetAttribute(k_av,     cudaFuncAttributeMaxDynamicSharedMemorySize, CA_SMEM);
    cudaFuncSetAttribute(k_scores, cudaFuncAttributeMaxDynamicSharedMemorySize, CAKT_SMEM);

    k_cvt   <<<(NQ4 + NP4) / 256, 256>>>(qkv_w, proj_w);
    gn_stats<<<NB * GROUPS, 256>>>(x, gn_w, gn_b);
    k_qkv   <<<dim3(T / 128, (3 * C) / 128, NB), 256>>>(qkv_b, x);
    k_scores<<<dim3(T / 128, T / 128, NB), 256, CAKT_SMEM>>>();
    k_lsum  <<<NB * T / 256, 256>>>();
    k_av    <<<dim3(C / 128, T / 128, NB), 256, CA_SMEM>>>();
    k_proj  <<<dim3(T / 128, C / 128, NB), 256>>>(proj_b, x, out);
}